// round 3
// baseline (speedup 1.0000x reference)
#include <cuda_runtime.h>
#include <cuda_bf16.h>

#define NGRID   10000
#define NSTEPS  730
#define LENF    15
#define NEARZEROF 1e-5f

__global__ __launch_bounds__(128, 1)
void hbv_kernel(const float* __restrict__ x_phy,     // [NSTEPS, NGRID, 3]
                const float* __restrict__ phy,       // [NGRID, 16]
                float* __restrict__ out)             // [NSTEPS, NGRID]
{
    int g = blockIdx.x * blockDim.x + threadIdx.x;
    if (g >= NGRID) return;

    // ---- per-cell parameters (de-normalized) ----
    const float* ps = phy + g * 16;
    float BETA   = ps[0]  * 5.0f   + 1.0f;
    float FC     = ps[1]  * 950.0f + 50.0f;
    float K0     = ps[2]  * 0.85f  + 0.05f;
    float K1     = ps[3]  * 0.49f  + 0.01f;
    float K2     = ps[4]  * 0.199f + 0.001f;
    float LP     = ps[5]  * 0.8f   + 0.2f;
    float PERC   = ps[6]  * 10.0f;
    float UZL    = ps[7]  * 100.0f;
    float TT     = ps[8]  * 5.0f   - 2.5f;
    float CFMAX  = ps[9]  * 9.5f   + 0.5f;
    float CFR    = ps[10] * 0.1f;
    float CWH    = ps[11] * 0.2f;
    float BETAET = ps[12] * 4.7f   + 0.3f;
    float C      = ps[13];
    float aa     = fmaxf(ps[14] * 2.9f, 0.0f) + 0.1f;
    float theta  = fmaxf(ps[15] * 6.5f, 0.0f) + 0.5f;

    float invFC     = 1.0f / FC;
    float invLPFC   = 1.0f / (LP * FC);
    float CFRCFMAX  = CFR * CFMAX;
    float invTheta  = 1.0f / theta;

    // ---- routing weights: gamma pdf on tgrid, normalized.
    // gammaln(aa) and aa*log(theta) cancel under normalization -> skip them.
    float w[LENF];
    float wsum = 0.0f;
#pragma unroll
    for (int k = 0; k < LENF; k++) {
        float tg = (float)k + 0.5f;
        float lw = (aa - 1.0f) * logf(tg) - tg * invTheta;
        float e  = expf(lw);
        w[k] = e;
        wsum += e;
    }
    float invw = 1.0f / wsum;
#pragma unroll
    for (int k = 0; k < LENF; k++) w[k] *= invw;

    // ---- state ----
    float snow = NEARZEROF, melt = NEARZEROF, sm = NEARZEROF,
          suz = NEARZEROF, slz = NEARZEROF;
    float hist[LENF - 1];
#pragma unroll
    for (int k = 0; k < LENF - 1; k++) hist[k] = 0.0f;

    const float* xp = x_phy + (size_t)g * 3;

    // first-step inputs
    float p  = __ldg(xp + 0);
    float tm = __ldg(xp + 1);
    float pe = __ldg(xp + 2);

    const int rowstride = NGRID * 3;

    for (int t = 0; t < NSTEPS; t++) {
        // prefetch next step (clamped, branch-free)
        int tn_idx = (t + 1 < NSTEPS) ? (t + 1) : (NSTEPS - 1);
        const float* xn = xp + (size_t)tn_idx * rowstride;
        float pn  = __ldg(xn + 0);
        float tmn = __ldg(xn + 1);
        float pen = __ldg(xn + 2);

        // soil_wet depends only on previous-step sm -> compute early
        // (overlaps 2 MUFU latencies with the snow chain)
        float soil_wet = fminf(__powf(sm * invFC, BETA), 1.0f);

        // ---- snow bucket ----
        float rain     = (tm >= TT) ? p : 0.0f;
        float snowfall = p - rain;
        snow += snowfall;
        float m = fminf(fmaxf(CFMAX * (tm - TT), 0.0f), snow);
        melt += m;
        snow -= m;
        float refr = fminf(fmaxf(CFRCFMAX * (TT - tm), 0.0f), melt);
        snow += refr;
        melt -= refr;
        float tosoil = fmaxf(melt - CWH * snow, 0.0f);
        melt -= tosoil;

        // ---- soil bucket ----
        float rt       = rain + tosoil;
        float recharge = rt * soil_wet;
        sm = sm + rt - recharge;
        float excess = fmaxf(sm - FC, 0.0f);
        sm -= excess;
        float evapfac = fminf(__powf(sm * invLPFC, BETAET), 1.0f);
        float etact   = fminf(sm, pe * evapfac);
        sm = fmaxf(sm - etact, NEARZEROF);
        float capillary = fminf(slz, C * slz * (1.0f - fminf(sm * invFC, 1.0f)));
        sm  = fmaxf(sm + capillary, NEARZEROF);
        slz = fmaxf(slz - capillary, NEARZEROF);

        // ---- response routine ----
        suz += recharge + excess;
        float percact = fminf(suz, PERC);
        suz -= percact;
        float q0 = K0 * fmaxf(suz - UZL, 0.0f);
        suz -= q0;
        float q1 = K1 * suz;
        suz -= q1;
        slz += percact;
        float q2 = K2 * slz;
        slz -= q2;
        float q = q0 + q1 + q2;

        // ---- fused 15-tap routing (shift register in registers) ----
        float qr = w[0] * q;
#pragma unroll
        for (int k = 1; k < LENF; k++) qr += w[k] * hist[k - 1];
#pragma unroll
        for (int k = LENF - 2; k > 0; k--) hist[k] = hist[k - 1];
        hist[0] = q;

        out[(size_t)t * NGRID + g] = qr;

        p = pn; tm = tmn; pe = pen;
    }
}

extern "C" void kernel_launch(void* const* d_in, const int* in_sizes, int n_in,
                              void* d_out, int out_size) {
    const float* x_phy = (const float*)d_in[0];
    const float* phy   = (const float*)d_in[1];
    float* out         = (float*)d_out;
    (void)in_sizes; (void)n_in; (void)out_size;

    int threads = 128;
    int blocks  = (NGRID + threads - 1) / threads;  // 79
    hbv_kernel<<<blocks, threads>>>(x_phy, phy, out);
}

// round 4
// speedup vs baseline: 1.9691x; 1.9691x over previous
#include <cuda_runtime.h>
#include <cuda_bf16.h>

#define NGRID   10000
#define NSTEPS  730
#define LENF    15
#define NEARZEROF 1e-5f
#define UNR     5          // 730 % 5 == 0

__global__ __launch_bounds__(128, 1)
void hbv_kernel(const float* __restrict__ x_phy,     // [NSTEPS, NGRID, 3]
                const float* __restrict__ phy,       // [NGRID, 16]
                float* __restrict__ out)             // [NSTEPS, NGRID]
{
    int g = blockIdx.x * blockDim.x + threadIdx.x;
    if (g >= NGRID) return;

    // ---- per-cell parameters (de-normalized) ----
    const float* ps = phy + g * 16;
    float BETA   = ps[0]  * 5.0f   + 1.0f;
    float FC     = ps[1]  * 950.0f + 50.0f;
    float K0     = ps[2]  * 0.85f  + 0.05f;
    float K1     = ps[3]  * 0.49f  + 0.01f;
    float K2     = ps[4]  * 0.199f + 0.001f;
    float LP     = ps[5]  * 0.8f   + 0.2f;
    float PERC   = ps[6]  * 10.0f;
    float UZL    = ps[7]  * 100.0f;
    float TT     = ps[8]  * 5.0f   - 2.5f;
    float CFMAX  = ps[9]  * 9.5f   + 0.5f;
    float CFR    = ps[10] * 0.1f;
    float CWH    = ps[11] * 0.2f;
    float BETAET = ps[12] * 4.7f   + 0.3f;
    float C      = ps[13];
    float aa     = fmaxf(ps[14] * 2.9f, 0.0f) + 0.1f;
    float theta  = fmaxf(ps[15] * 6.5f, 0.0f) + 0.5f;

    float invFC     = 1.0f / FC;
    float invLPFC   = 1.0f / (LP * FC);
    float CFRCFMAX  = CFR * CFMAX;
    float invTheta  = 1.0f / theta;

    // ---- routing weights: gamma pdf on tgrid, normalized.
    // gammaln(aa) and aa*log(theta) cancel under normalization -> skip them.
    float w[LENF];
    float wsum = 0.0f;
#pragma unroll
    for (int k = 0; k < LENF; k++) {
        float tg = (float)k + 0.5f;
        float lw = (aa - 1.0f) * logf(tg) - tg * invTheta;
        float e  = expf(lw);
        w[k] = e;
        wsum += e;
    }
    float invw = 1.0f / wsum;
#pragma unroll
    for (int k = 0; k < LENF; k++) w[k] *= invw;

    // ---- state ----
    float snow = NEARZEROF, melt = NEARZEROF, sm = NEARZEROF,
          suz = NEARZEROF, slz = NEARZEROF;
    float hist[LENF - 1];
#pragma unroll
    for (int k = 0; k < LENF - 1; k++) hist[k] = 0.0f;

    const int rowstride = NGRID * 3;
    const float* xbase = x_phy + (size_t)g * 3;

    // ---- preload first group of UNR steps (batched: MLP = 3*UNR) ----
    float bp[UNR], btm[UNR], bpe[UNR];
#pragma unroll
    for (int u = 0; u < UNR; u++) {
        const float* xn = xbase + (size_t)u * rowstride;
        bp[u]  = __ldg(xn + 0);
        btm[u] = __ldg(xn + 1);
        bpe[u] = __ldg(xn + 2);
    }

    float* orow = out + g;

    for (int base = 0; base < NSTEPS; base += UNR) {
        // ---- batched prefetch of the NEXT group (15 loads in flight) ----
        float np[UNR], ntm[UNR], npe[UNR];
#pragma unroll
        for (int u = 0; u < UNR; u++) {
            int idx = base + UNR + u;
            if (idx >= NSTEPS) idx = NSTEPS - 1;   // harmless clamped reload
            const float* xn = xbase + (size_t)idx * rowstride;
            np[u]  = __ldg(xn + 0);
            ntm[u] = __ldg(xn + 1);
            npe[u] = __ldg(xn + 2);
        }

        // ---- UNR step bodies on the current group ----
#pragma unroll
        for (int u = 0; u < UNR; u++) {
            float p  = bp[u];
            float tm = btm[u];
            float pe = bpe[u];

            // soil_wet depends only on previous-step sm -> compute early
            float soil_wet = fminf(__powf(sm * invFC, BETA), 1.0f);

            // ---- snow bucket ----
            float rain     = (tm >= TT) ? p : 0.0f;
            float snowfall = p - rain;
            snow += snowfall;
            float m = fminf(fmaxf(CFMAX * (tm - TT), 0.0f), snow);
            melt += m;
            snow -= m;
            float refr = fminf(fmaxf(CFRCFMAX * (TT - tm), 0.0f), melt);
            snow += refr;
            melt -= refr;
            float tosoil = fmaxf(melt - CWH * snow, 0.0f);
            melt -= tosoil;

            // ---- soil bucket ----
            float rt       = rain + tosoil;
            float recharge = rt * soil_wet;
            sm = sm + rt - recharge;
            float excess = fmaxf(sm - FC, 0.0f);
            sm -= excess;
            float evapfac = fminf(__powf(sm * invLPFC, BETAET), 1.0f);
            float etact   = fminf(sm, pe * evapfac);
            sm = fmaxf(sm - etact, NEARZEROF);
            float capillary = fminf(slz, C * slz * (1.0f - fminf(sm * invFC, 1.0f)));
            sm  = fmaxf(sm + capillary, NEARZEROF);
            slz = fmaxf(slz - capillary, NEARZEROF);

            // ---- response routine ----
            suz += recharge + excess;
            float percact = fminf(suz, PERC);
            suz -= percact;
            float q0 = K0 * fmaxf(suz - UZL, 0.0f);
            suz -= q0;
            float q1 = K1 * suz;
            suz -= q1;
            slz += percact;
            float q2 = K2 * slz;
            slz -= q2;
            float q = q0 + q1 + q2;

            // ---- fused 15-tap routing (register shift) ----
            float qr = w[0] * q;
#pragma unroll
            for (int k = 1; k < LENF; k++) qr += w[k] * hist[k - 1];
#pragma unroll
            for (int k = LENF - 2; k > 0; k--) hist[k] = hist[k - 1];
            hist[0] = q;

            orow[(size_t)(base + u) * NGRID] = qr;
        }

        // ---- rotate prefetch buffers ----
#pragma unroll
        for (int u = 0; u < UNR; u++) {
            bp[u] = np[u]; btm[u] = ntm[u]; bpe[u] = npe[u];
        }
    }
}

extern "C" void kernel_launch(void* const* d_in, const int* in_sizes, int n_in,
                              void* d_out, int out_size) {
    const float* x_phy = (const float*)d_in[0];
    const float* phy   = (const float*)d_in[1];
    float* out         = (float*)d_out;
    (void)in_sizes; (void)n_in; (void)out_size;

    int threads = 128;
    int blocks  = (NGRID + threads - 1) / threads;  // 79
    hbv_kernel<<<blocks, threads>>>(x_phy, phy, out);
}

// round 5
// speedup vs baseline: 2.0700x; 1.0512x over previous
#include <cuda_runtime.h>
#include <cuda_bf16.h>

#define NGRID   10000
#define NSTEPS  730
#define LENF    15
#define NEARZEROF 1e-5f
#define UNR     5          // 730 % 5 == 0

__global__ __launch_bounds__(128, 1)
void hbv_kernel(const float* __restrict__ x_phy,     // [NSTEPS, NGRID, 3]
                const float* __restrict__ phy,       // [NGRID, 16]
                float* __restrict__ out)             // [NSTEPS, NGRID]
{
    int g = blockIdx.x * blockDim.x + threadIdx.x;
    if (g >= NGRID) return;

    // ---- per-cell parameters (de-normalized) ----
    const float* ps = phy + g * 16;
    float BETA   = ps[0]  * 5.0f   + 1.0f;
    float FC     = ps[1]  * 950.0f + 50.0f;
    float K0     = ps[2]  * 0.85f  + 0.05f;
    float K1     = ps[3]  * 0.49f  + 0.01f;
    float K2     = ps[4]  * 0.199f + 0.001f;
    float LP     = ps[5]  * 0.8f   + 0.2f;
    float PERC   = ps[6]  * 10.0f;
    float UZL    = ps[7]  * 100.0f;
    float TT     = ps[8]  * 5.0f   - 2.5f;
    float CFMAX  = ps[9]  * 9.5f   + 0.5f;
    float CFR    = ps[10] * 0.1f;
    float CWH    = ps[11] * 0.2f;
    float BETAET = ps[12] * 4.7f   + 0.3f;
    float C      = ps[13];
    float aa     = fmaxf(ps[14] * 2.9f, 0.0f) + 0.1f;
    float theta  = fmaxf(ps[15] * 6.5f, 0.0f) + 0.5f;

    float invFC     = 1.0f / FC;
    float invLPFC   = 1.0f / (LP * FC);
    float CFRCFMAX  = CFR * CFMAX;
    float invTheta  = 1.0f / theta;

    // ---- routing weights: gamma pdf, normalized (gammaln & a*log(theta) cancel) ----
    float w[LENF];
    float wsum = 0.0f;
#pragma unroll
    for (int k = 0; k < LENF; k++) {
        float tg = (float)k + 0.5f;
        float e  = expf((aa - 1.0f) * logf(tg) - tg * invTheta);
        w[k] = e;
        wsum += e;
    }
    float invw = 1.0f / wsum;
#pragma unroll
    for (int k = 0; k < LENF; k++) w[k] *= invw;

    // ---- state ----
    float snow = NEARZEROF, melt = NEARZEROF, sm = NEARZEROF,
          suz = NEARZEROF, slz = NEARZEROF;
    // off-chain capillary precompute from slz
    float cslz = C * slz;            // C*slz
    float kcap = cslz * invFC;       // C*slz/FC
    float hist[LENF - 1];
#pragma unroll
    for (int k = 0; k < LENF - 1; k++) hist[k] = 0.0f;

    const int rowstride = NGRID * 3;
    const float* xbase = x_phy + (size_t)g * 3;

    // ---- preload 2 groups deep (MLP up to 30) ----
    float Ap[UNR], Atm[UNR], Ape[UNR];   // current group
    float Bp[UNR], Btm[UNR], Bpe[UNR];   // next group
#pragma unroll
    for (int u = 0; u < UNR; u++) {
        const float* xa = xbase + (size_t)u * rowstride;
        Ap[u]  = __ldg(xa + 0);  Atm[u] = __ldg(xa + 1);  Ape[u] = __ldg(xa + 2);
        const float* xb = xbase + (size_t)(u + UNR) * rowstride;
        Bp[u]  = __ldg(xb + 0);  Btm[u] = __ldg(xb + 1);  Bpe[u] = __ldg(xb + 2);
    }

    float* orow = out + g;

    for (int base = 0; base < NSTEPS; base += UNR) {
        // ---- prefetch group base+2*UNR (distance 10 steps) ----
        float Cp[UNR], Ctm[UNR], Cpe[UNR];
#pragma unroll
        for (int u = 0; u < UNR; u++) {
            int idx = base + 2 * UNR + u;
            if (idx >= NSTEPS) idx = NSTEPS - 1;   // harmless clamped reload
            const float* xn = xbase + (size_t)idx * rowstride;
            Cp[u]  = __ldg(xn + 0);
            Ctm[u] = __ldg(xn + 1);
            Cpe[u] = __ldg(xn + 2);
        }

#pragma unroll
        for (int u = 0; u < UNR; u++) {
            float p  = Ap[u];
            float tm = Atm[u];
            float pe = Ape[u];

            // input-only precomputes (off loop-carried chain; ptxas hoists)
            float rain     = (tm >= TT) ? p : 0.0f;
            float snowfall = p - rain;
            float mpot     = fmaxf(CFMAX    * (tm - TT), 0.0f);
            float rpot     = fmaxf(CFRCFMAX * (TT - tm), 0.0f);

            // soil_wet from previous-step sm: MUFU chain overlaps snow chain
            float soil_wet = fminf(__powf(sm * invFC, BETA), 1.0f);
            float om_sw    = 1.0f - soil_wet;

            // ---- snow bucket ----
            snow += snowfall;
            float m = fminf(mpot, snow);
            melt += m;
            snow -= m;
            float refr = fminf(rpot, melt);
            snow += refr;
            melt -= refr;
            float tosoil = fmaxf(melt - CWH * snow, 0.0f);
            melt -= tosoil;

            // ---- soil bucket (chain-shortened, exact) ----
            float rt       = rain + tosoil;
            float recharge = rt * soil_wet;                 // off-chain (for suz)
            float sm_pre   = fmaf(rt, om_sw, sm);           // sm + rt - recharge
            float sm_c     = fminf(sm_pre, FC);             // == sm_pre - excess
            float excess   = sm_pre - sm_c;                 // off-chain (for suz)
            // evapfac from sm_pre is EXACT (see derivation): parallel to clamp
            float evapfac  = fminf(__powf(sm_pre * invLPFC, BETAET), 1.0f);
            float sm_et    = fmaxf(fmaf(-pe, evapfac, sm_c), NEARZEROF);
            // capillary: sm_et <= FC, so min(sm/FC,1)=sm/FC; k,cslz from prev slz
            float cap      = fminf(slz, fmaf(-kcap, sm_et, cslz));
            sm             = fmaxf(sm_et + cap, NEARZEROF);
            slz            = fmaxf(slz - cap, NEARZEROF);

            // ---- response routine ----
            suz += recharge + excess;
            float percact = fminf(suz, PERC);
            suz -= percact;
            float q0 = K0 * fmaxf(suz - UZL, 0.0f);
            suz -= q0;
            float q1 = K1 * suz;
            suz -= q1;
            slz += percact;
            float q2 = K2 * slz;
            slz -= q2;
            float q = q0 + q1 + q2;

            // precompute next step's capillary coefficients (off-chain)
            cslz = C * slz;
            kcap = cslz * invFC;

            // ---- fused 15-tap routing (register shift) ----
            float qr = w[0] * q;
#pragma unroll
            for (int k = 1; k < LENF; k++) qr += w[k] * hist[k - 1];
#pragma unroll
            for (int k = LENF - 2; k > 0; k--) hist[k] = hist[k - 1];
            hist[0] = q;

            orow[(size_t)(base + u) * NGRID] = qr;
        }

        // ---- rotate buffers A<-B<-C ----
#pragma unroll
        for (int u = 0; u < UNR; u++) {
            Ap[u] = Bp[u];  Atm[u] = Btm[u];  Ape[u] = Bpe[u];
            Bp[u] = Cp[u];  Btm[u] = Ctm[u];  Bpe[u] = Cpe[u];
        }
    }
}

extern "C" void kernel_launch(void* const* d_in, const int* in_sizes, int n_in,
                              void* d_out, int out_size) {
    const float* x_phy = (const float*)d_in[0];
    const float* phy   = (const float*)d_in[1];
    float* out         = (float*)d_out;
    (void)in_sizes; (void)n_in; (void)out_size;

    int threads = 128;
    int blocks  = (NGRID + threads - 1) / threads;  // 79
    hbv_kernel<<<blocks, threads>>>(x_phy, phy, out);
}